// round 12
// baseline (speedup 1.0000x reference)
#include <cuda_runtime.h>
#include <cuda_bf16.h>
#include <cstdint>

// WeightAndSum: gated segment sum. Single-wave persistent layout.
// cp.async (LDGSTS) staging into per-warp private SMEM rings moves
// bytes-in-flight out of the register file (the R9 bottleneck):
// 4-stage ring x 4 rows x 512B per warp, warp-private commit/wait groups
// (each lane consumes exactly the bytes it copied -> no barriers).
//   logits = feats @ W + b   (atom logits output, pre-sigmoid)
//   out[g] = sum_{seg[r]==g} sigmoid(logit_r) * feats[r]
// Sorted segments -> register accumulation, atomic flush on segment change.
// Reduction: fold-and-select multi-value butterfly (13 SHFL per 4 rows).

#define F_DIM 128
#define F_VEC 32                      // float4s per row
#define FULL  0xFFFFFFFFu
#define DEPTH 4                       // ring stages (power of 2)
#define ROW_BYTES 512
#define STAGE_BYTES (4 * ROW_BYTES)   // 4 rows per group = 2048
#define RING_BYTES (DEPTH * STAGE_BYTES)   // 8192 per warp
#define BLOCK_SMEM (8 * RING_BYTES)   // 8 warps = 65536

__device__ __forceinline__ void cp16(uint32_t dst, const float4* src) {
    asm volatile("cp.async.cg.shared.global [%0], [%1], 16;\n"
                 :: "r"(dst), "l"(src) : "memory");
}
__device__ __forceinline__ void cp_commit() {
    asm volatile("cp.async.commit_group;\n" ::: "memory");
}
__device__ __forceinline__ void cp_wait3() {
    asm volatile("cp.async.wait_group 3;\n" ::: "memory");
}

__global__ __launch_bounds__(256, 3)
void was_kernel(
    // atom job
    const float* __restrict__ a_feats, const float* __restrict__ a_W,
    const float* __restrict__ a_b, const int* __restrict__ a_seg,
    float* __restrict__ a_out, float* __restrict__ a_logits,
    int a_n, int a_rpw, int a_blocks,
    // vir job
    const float* __restrict__ v_feats, const float* __restrict__ v_W,
    const float* __restrict__ v_b, const int* __restrict__ v_seg,
    float* __restrict__ v_out,
    int v_n, int v_rpw)
{
    extern __shared__ char smem[];

    const float* feats;
    const float* Wp;
    const float* bp;
    const int*   seg;
    float*       outp;
    float*       logits;
    int n, rpw, block_in_job;

    if (blockIdx.x < (unsigned)a_blocks) {
        feats = a_feats; Wp = a_W; bp = a_b; seg = a_seg;
        outp = a_out; logits = a_logits; n = a_n; rpw = a_rpw;
        block_in_job = blockIdx.x;
    } else {
        feats = v_feats; Wp = v_W; bp = v_b; seg = v_seg;
        outp = v_out; logits = nullptr; n = v_n; rpw = v_rpw;
        block_in_job = blockIdx.x - a_blocks;
    }

    const int lane  = threadIdx.x & 31;
    const int wib   = threadIdx.x >> 5;
    const int gwarp = block_in_job * (blockDim.x >> 5) + wib;

    long start = (long)gwarp * rpw;          // rpw is a multiple of 4
    if (start >= n) return;
    long end = start + rpw;
    if (end > n) end = n;                    // n, start, end all multiples of 4

    const float4 Wv  = reinterpret_cast<const float4*>(Wp)[lane];
    const float bias = bp[0];
    // lane-folded source pointer
    const float4* fl = reinterpret_cast<const float4*>(feats) + lane;

    // per-warp private ring
    char* ring = smem + wib * RING_BYTES;
    char* ringl = ring + lane * 16;
    const uint32_t ring_s = (uint32_t)__cvta_generic_to_shared(ring) + lane * 16;

    const bool lo16 = (lane < 16);
    const bool lo8  = ((lane & 8) == 0);

    float4 acc = make_float4(0.f, 0.f, 0.f, 0.f);
    int cur_seg = __ldg(&seg[start]);

    const int g_count = (int)((end - start) >> 2);

    // ---- prologue: fill DEPTH-1 stages ----
    #pragma unroll
    for (int gi = 0; gi < DEPTH - 1; ++gi) {
        if (gi < g_count) {
            const float4* src = fl + (start + (long)gi * 4) * F_VEC;
            uint32_t dst = ring_s + (gi & (DEPTH - 1)) * STAGE_BYTES;
            cp16(dst + 0 * ROW_BYTES, src + 0 * F_VEC);
            cp16(dst + 1 * ROW_BYTES, src + 1 * F_VEC);
            cp16(dst + 2 * ROW_BYTES, src + 2 * F_VEC);
            cp16(dst + 3 * ROW_BYTES, src + 3 * F_VEC);
        }
        cp_commit();
    }

    int4 sv = *reinterpret_cast<const int4*>(seg + start);

    for (int g = 0; g < g_count; ++g) {
        // issue DEPTH-1 groups ahead
        int ga = g + DEPTH - 1;
        if (ga < g_count) {
            const float4* src = fl + (start + (long)ga * 4) * F_VEC;
            uint32_t dst = ring_s + (ga & (DEPTH - 1)) * STAGE_BYTES;
            cp16(dst + 0 * ROW_BYTES, src + 0 * F_VEC);
            cp16(dst + 1 * ROW_BYTES, src + 1 * F_VEC);
            cp16(dst + 2 * ROW_BYTES, src + 2 * F_VEC);
            cp16(dst + 3 * ROW_BYTES, src + 3 * F_VEC);
        }
        cp_commit();

        long r = start + (long)g * 4;
        int4 sn;
        if (g + 1 < g_count)
            sn = *reinterpret_cast<const int4*>(seg + r + 4);

        cp_wait3();     // group g complete (own-lane bytes visible)

        char* st = ringl + (g & (DEPTH - 1)) * STAGE_BYTES;
        float4 f0 = *reinterpret_cast<const float4*>(st + 0 * ROW_BYTES);
        float4 f1 = *reinterpret_cast<const float4*>(st + 1 * ROW_BYTES);
        float4 f2 = *reinterpret_cast<const float4*>(st + 2 * ROW_BYTES);
        float4 f3 = *reinterpret_cast<const float4*>(st + 3 * ROW_BYTES);

        // 4 partial dots
        float p0 = f0.x * Wv.x + f0.y * Wv.y + f0.z * Wv.z + f0.w * Wv.w;
        float p1 = f1.x * Wv.x + f1.y * Wv.y + f1.z * Wv.z + f1.w * Wv.w;
        float p2 = f2.x * Wv.x + f2.y * Wv.y + f2.z * Wv.z + f2.w * Wv.w;
        float p3 = f3.x * Wv.x + f3.y * Wv.y + f3.z * Wv.z + f3.w * Wv.w;

        // fold-and-select multi-value reduction (13 SHFL total)
        p0 += __shfl_xor_sync(FULL, p0, 16);
        p1 += __shfl_xor_sync(FULL, p1, 16);
        p2 += __shfl_xor_sync(FULL, p2, 16);
        p3 += __shfl_xor_sync(FULL, p3, 16);
        float a = lo16 ? p0 : p1;
        float b = lo16 ? p2 : p3;
        a += __shfl_xor_sync(FULL, a, 8);
        b += __shfl_xor_sync(FULL, b, 8);
        float c = lo8 ? a : b;
        c += __shfl_xor_sync(FULL, c, 4);
        c += __shfl_xor_sync(FULL, c, 2);
        c += __shfl_xor_sync(FULL, c, 1);
        float l0 = __shfl_sync(FULL, c, 0)  + bias;
        float l1 = __shfl_sync(FULL, c, 16) + bias;
        float l2 = __shfl_sync(FULL, c, 8)  + bias;
        float l3 = __shfl_sync(FULL, c, 24) + bias;

        if (logits != nullptr && lane == 0) {
            __stcs(reinterpret_cast<float4*>(logits + r),
                   make_float4(l0, l1, l2, l3));
        }

        float w0 = 1.0f / (1.0f + __expf(-l0));
        float w1 = 1.0f / (1.0f + __expf(-l1));
        float w2 = 1.0f / (1.0f + __expf(-l2));
        float w3 = 1.0f / (1.0f + __expf(-l3));

        // sequential segment handling (sorted; changes rare)
        #pragma unroll
        for (int k = 0; k < 4; ++k) {
            int s     = (k == 0) ? sv.x : (k == 1) ? sv.y : (k == 2) ? sv.z : sv.w;
            float w   = (k == 0) ? w0   : (k == 1) ? w1   : (k == 2) ? w2   : w3;
            float4 f  = (k == 0) ? f0   : (k == 1) ? f1   : (k == 2) ? f2   : f3;
            if (s != cur_seg) {
                float* o = outp + (long)cur_seg * F_DIM + lane * 4;
                atomicAdd(o + 0, acc.x);
                atomicAdd(o + 1, acc.y);
                atomicAdd(o + 2, acc.z);
                atomicAdd(o + 3, acc.w);
                acc = make_float4(0.f, 0.f, 0.f, 0.f);
                cur_seg = s;
            }
            acc.x += w * f.x;
            acc.y += w * f.y;
            acc.z += w * f.z;
            acc.w += w * f.w;
        }

        sv = sn;
    }

    // final flush
    float* o = outp + (long)cur_seg * F_DIM + lane * 4;
    atomicAdd(o + 0, acc.x);
    atomicAdd(o + 1, acc.y);
    atomicAdd(o + 2, acc.z);
    atomicAdd(o + 3, acc.w);
}

extern "C" void kernel_launch(void* const* d_in, const int* in_sizes, int n_in,
                              void* d_out, int out_size)
{
    const float* atom_feats = (const float*)d_in[0];
    const float* vir_feats  = (const float*)d_in[1];
    const float* W_atom     = (const float*)d_in[2];
    const float* b_atom     = (const float*)d_in[3];
    const float* W_vir      = (const float*)d_in[4];
    const float* b_vir      = (const float*)d_in[5];
    const int*   atom_seg   = (const int*)d_in[6];
    const int*   vir_seg    = (const int*)d_in[7];

    const int n_atom = in_sizes[0] / F_DIM;
    const int n_vir  = in_sizes[1] / F_DIM;
    // out layout: [G,128] atom sums | [G,128] vir sums | [n_atom] logits
    const int G = (out_size - n_atom) / (2 * F_DIM);

    float* out       = (float*)d_out;
    float* out_atom  = out;
    float* out_vir   = out + (size_t)G * F_DIM;
    float* logits    = out + (size_t)2 * G * F_DIM;

    cudaMemsetAsync(out, 0, (size_t)2 * G * F_DIM * sizeof(float), 0);

    static int smem_set = 0;
    if (!smem_set) {
        cudaFuncSetAttribute(was_kernel,
                             cudaFuncAttributeMaxDynamicSharedMemorySize,
                             BLOCK_SMEM);
        smem_set = 1;
    }

    // Single wave: 148 SMs * 3 blocks/SM (64KB smem/block, 192KB/SM)
    const int threads = 256;
    const int wpb = threads / 32;
    const int total_blocks = 148 * 3;

    long total_rows = (long)n_atom + n_vir;
    int a_blocks = (int)(((long)total_blocks * n_atom + total_rows - 1) / total_rows);
    if (a_blocks < 1) a_blocks = 1;
    if (a_blocks > total_blocks - 1) a_blocks = total_blocks - 1;
    int v_blocks = total_blocks - a_blocks;

    int a_rpw = (n_atom + a_blocks * wpb - 1) / (a_blocks * wpb);
    a_rpw = (a_rpw + 3) & ~3;
    int v_rpw = (n_vir + v_blocks * wpb - 1) / (v_blocks * wpb);
    v_rpw = (v_rpw + 3) & ~3;

    was_kernel<<<total_blocks, threads, BLOCK_SMEM, 0>>>(
        atom_feats, W_atom, b_atom, atom_seg, out_atom, logits,
        n_atom, a_rpw, a_blocks,
        vir_feats, W_vir, b_vir, vir_seg, out_vir,
        n_vir, v_rpw);
}

// round 13
// speedup vs baseline: 1.2085x; 1.2085x over previous
#include <cuda_runtime.h>
#include <cuda_bf16.h>

// WeightAndSum: gated segment sum. Single-wave persistent layout,
// 4-row groups with depth-2 software pipeline (8 outstanding LDG.128/warp).
//   logits = feats @ W + b   (atom logits output, pre-sigmoid)
//   out[g] = sum_{seg[r]==g} sigmoid(logit_r) * feats[r]
// Sorted segments -> register accumulation, atomic flush on segment change.
// Reduction: fold-and-select multi-value butterfly (13 SHFL per 4 rows).
// Epilogue: ONE sigmoid per lane on the folded sum, then broadcast the 4
// gate values (replaces 4 redundant per-lane sigmoids -> -12 MUFU/group);
// logit broadcasts only on atom warps (uniform branch).

#define F_DIM 128
#define F_VEC 32          // float4s per row
#define FULL  0xFFFFFFFFu

__global__ __launch_bounds__(256, 3)
void was_kernel(
    // atom job
    const float* __restrict__ a_feats, const float* __restrict__ a_W,
    const float* __restrict__ a_b, const int* __restrict__ a_seg,
    float* __restrict__ a_out, float* __restrict__ a_logits,
    int a_n, int a_rpw, int a_blocks,
    // vir job
    const float* __restrict__ v_feats, const float* __restrict__ v_W,
    const float* __restrict__ v_b, const int* __restrict__ v_seg,
    float* __restrict__ v_out,
    int v_n, int v_rpw)
{
    const float* feats;
    const float* Wp;
    const float* bp;
    const int*   seg;
    float*       outp;
    float*       logits;
    int n, rpw, block_in_job;

    if (blockIdx.x < (unsigned)a_blocks) {
        feats = a_feats; Wp = a_W; bp = a_b; seg = a_seg;
        outp = a_out; logits = a_logits; n = a_n; rpw = a_rpw;
        block_in_job = blockIdx.x;
    } else {
        feats = v_feats; Wp = v_W; bp = v_b; seg = v_seg;
        outp = v_out; logits = nullptr; n = v_n; rpw = v_rpw;
        block_in_job = blockIdx.x - a_blocks;
    }

    const int lane  = threadIdx.x & 31;
    const int gwarp = block_in_job * (blockDim.x >> 5) + (threadIdx.x >> 5);

    long start = (long)gwarp * rpw;          // rpw is a multiple of 4
    if (start >= n) return;
    long end = start + rpw;
    if (end > n) end = n;                    // n is a multiple of 4

    const float4 Wv  = reinterpret_cast<const float4*>(Wp)[lane];
    const float bias = bp[0];
    const float4* frows = reinterpret_cast<const float4*>(feats);

    const bool lo16 = (lane < 16);
    const bool lo8  = ((lane & 8) == 0);

    float4 acc = make_float4(0.f, 0.f, 0.f, 0.f);
    int cur_seg = __ldg(&seg[start]);

    // ---- depth-2 pipeline: prefetch first 4-row group ----
    float4 f0 = __ldcs(&frows[(start + 0) * F_VEC + lane]);
    float4 f1 = __ldcs(&frows[(start + 1) * F_VEC + lane]);
    float4 f2 = __ldcs(&frows[(start + 2) * F_VEC + lane]);
    float4 f3 = __ldcs(&frows[(start + 3) * F_VEC + lane]);
    int4  sv  = *reinterpret_cast<const int4*>(seg + start);

    for (long r = start; r < end; r += 4) {
        // prefetch next group before consuming current
        float4 g0, g1, g2, g3;
        int4 sn;
        if (r + 4 < end) {
            g0 = __ldcs(&frows[(r + 4) * F_VEC + lane]);
            g1 = __ldcs(&frows[(r + 5) * F_VEC + lane]);
            g2 = __ldcs(&frows[(r + 6) * F_VEC + lane]);
            g3 = __ldcs(&frows[(r + 7) * F_VEC + lane]);
            sn = *reinterpret_cast<const int4*>(seg + r + 4);
        }

        // 4 partial dots
        float p0 = f0.x * Wv.x + f0.y * Wv.y + f0.z * Wv.z + f0.w * Wv.w;
        float p1 = f1.x * Wv.x + f1.y * Wv.y + f1.z * Wv.z + f1.w * Wv.w;
        float p2 = f2.x * Wv.x + f2.y * Wv.y + f2.z * Wv.z + f2.w * Wv.w;
        float p3 = f3.x * Wv.x + f3.y * Wv.y + f3.z * Wv.z + f3.w * Wv.w;

        // fold-and-select multi-value reduction (13 SHFL total)
        p0 += __shfl_xor_sync(FULL, p0, 16);
        p1 += __shfl_xor_sync(FULL, p1, 16);
        p2 += __shfl_xor_sync(FULL, p2, 16);
        p3 += __shfl_xor_sync(FULL, p3, 16);
        float a = lo16 ? p0 : p1;           // lanes 0-15: S0, 16-31: S1
        float b = lo16 ? p2 : p3;           // lanes 0-15: S2, 16-31: S3
        a += __shfl_xor_sync(FULL, a, 8);
        b += __shfl_xor_sync(FULL, b, 8);
        float c = lo8 ? a : b;              // 0-7:S0 8-15:S2 16-23:S1 24-31:S3
        c += __shfl_xor_sync(FULL, c, 4);
        c += __shfl_xor_sync(FULL, c, 2);
        c += __shfl_xor_sync(FULL, c, 1);

        // ONE sigmoid per lane on its folded sum, then broadcast gates.
        float cb = c + bias;
        float wl = 1.0f / (1.0f + __expf(-cb));
        float w0 = __shfl_sync(FULL, wl, 0);
        float w1 = __shfl_sync(FULL, wl, 16);
        float w2 = __shfl_sync(FULL, wl, 8);
        float w3 = __shfl_sync(FULL, wl, 24);

        if (logits != nullptr) {            // uniform per warp
            float l0 = __shfl_sync(FULL, cb, 0);
            float l1 = __shfl_sync(FULL, cb, 16);
            float l2 = __shfl_sync(FULL, cb, 8);
            float l3 = __shfl_sync(FULL, cb, 24);
            if (lane == 0) {
                __stcs(reinterpret_cast<float4*>(logits + r),
                       make_float4(l0, l1, l2, l3));
            }
        }

        // sequential segment handling (sorted; changes rare)
        #pragma unroll
        for (int k = 0; k < 4; ++k) {
            int s     = (k == 0) ? sv.x : (k == 1) ? sv.y : (k == 2) ? sv.z : sv.w;
            float w   = (k == 0) ? w0   : (k == 1) ? w1   : (k == 2) ? w2   : w3;
            float4 f  = (k == 0) ? f0   : (k == 1) ? f1   : (k == 2) ? f2   : f3;
            if (s != cur_seg) {
                float* o = outp + (long)cur_seg * F_DIM + lane * 4;
                atomicAdd(o + 0, acc.x);
                atomicAdd(o + 1, acc.y);
                atomicAdd(o + 2, acc.z);
                atomicAdd(o + 3, acc.w);
                acc = make_float4(0.f, 0.f, 0.f, 0.f);
                cur_seg = s;
            }
            acc.x += w * f.x;
            acc.y += w * f.y;
            acc.z += w * f.z;
            acc.w += w * f.w;
        }

        f0 = g0; f1 = g1; f2 = g2; f3 = g3; sv = sn;
    }

    // final flush
    float* o = outp + (long)cur_seg * F_DIM + lane * 4;
    atomicAdd(o + 0, acc.x);
    atomicAdd(o + 1, acc.y);
    atomicAdd(o + 2, acc.z);
    atomicAdd(o + 3, acc.w);
}

extern "C" void kernel_launch(void* const* d_in, const int* in_sizes, int n_in,
                              void* d_out, int out_size)
{
    const float* atom_feats = (const float*)d_in[0];
    const float* vir_feats  = (const float*)d_in[1];
    const float* W_atom     = (const float*)d_in[2];
    const float* b_atom     = (const float*)d_in[3];
    const float* W_vir      = (const float*)d_in[4];
    const float* b_vir      = (const float*)d_in[5];
    const int*   atom_seg   = (const int*)d_in[6];
    const int*   vir_seg    = (const int*)d_in[7];

    const int n_atom = in_sizes[0] / F_DIM;
    const int n_vir  = in_sizes[1] / F_DIM;
    // out layout: [G,128] atom sums | [G,128] vir sums | [n_atom] logits
    const int G = (out_size - n_atom) / (2 * F_DIM);

    float* out       = (float*)d_out;
    float* out_atom  = out;
    float* out_vir   = out + (size_t)G * F_DIM;
    float* logits    = out + (size_t)2 * G * F_DIM;

    cudaMemsetAsync(out, 0, (size_t)2 * G * F_DIM * sizeof(float), 0);

    // Single wave: 148 SMs * 3 blocks/SM (launch_bounds(256,3))
    const int threads = 256;
    const int wpb = threads / 32;
    const int total_blocks = 148 * 3;

    long total_rows = (long)n_atom + n_vir;
    int a_blocks = (int)(((long)total_blocks * n_atom + total_rows - 1) / total_rows);
    if (a_blocks < 1) a_blocks = 1;
    if (a_blocks > total_blocks - 1) a_blocks = total_blocks - 1;
    int v_blocks = total_blocks - a_blocks;

    int a_rpw = (n_atom + a_blocks * wpb - 1) / (a_blocks * wpb);
    a_rpw = (a_rpw + 3) & ~3;
    int v_rpw = (n_vir + v_blocks * wpb - 1) / (v_blocks * wpb);
    v_rpw = (v_rpw + 3) & ~3;

    was_kernel<<<total_blocks, threads, 0, 0>>>(
        atom_feats, W_atom, b_atom, atom_seg, out_atom, logits,
        n_atom, a_rpw, a_blocks,
        vir_feats, W_vir, b_vir, vir_seg, out_vir,
        n_vir, v_rpw);
}